// round 9
// baseline (speedup 1.0000x reference)
#include <cuda_runtime.h>
#include <math.h>
#include <stdint.h>

// Problem constants
#define TT   131072   // tokens
#define D_IN 256      // input dim
#define HH   128      // per-direction hidden
#define G4   512      // 4*HH gate rows
#define HID  256      // bidirectional hidden
#define TAGS 10
#define NSEG 1024

// Scratch (device globals — no allocation allowed in kernel_launch)
__device__ float g_pre[2][TT][G4];   // pre-activations per direction (original token order)
__device__ float g_hs[TT][HID];      // [hf | hb] concatenated
__device__ float g_att[TT];          // attention logits

// Fast activations: __expf (EX2) + __fdividef (~2 ulp). Inf-safe saturation.
__device__ __forceinline__ float fsigmoid(float x) {
    return __fdividef(1.0f, 1.0f + __expf(-x));
}
__device__ __forceinline__ float ftanh(float x) {
    return 1.0f - __fdividef(2.0f, __expf(2.0f * x) + 1.0f);
}
// Accurate tanh for the (non-recurrent) attention path
__device__ __forceinline__ float tanh_acc(float x) {
    return 1.0f - 2.0f / (__expf(2.0f * x) + 1.0f);
}

// Packed dual-FMA (Blackwell f32x2). acc.{lo,hi} += a.{lo,hi} * b.{lo,hi}
__device__ __forceinline__ void ffma2(unsigned long long& acc,
                                      unsigned long long a,
                                      unsigned long long b) {
    asm("fma.rn.f32x2 %0, %1, %2, %0;" : "+l"(acc) : "l"(a), "l"(b));
}

__device__ __forceinline__ uint32_t smem_u32(const void* p) {
    uint32_t a;
    asm("{ .reg .u64 t; cvta.to.shared.u64 t, %1; cvt.u32.u64 %0, t; }"
        : "=r"(a) : "l"(p));
    return a;
}

// Cluster-scope acquire wait on a local mbarrier (spin on try_wait.parity)
__device__ __forceinline__ void mbar_wait_cluster(uint32_t addr, uint32_t parity) {
    uint32_t done;
    asm volatile(
        "{\n\t.reg .pred p;\n\t"
        "mbarrier.try_wait.parity.acquire.cluster.shared::cta.b64 p, [%1], %2;\n\t"
        "selp.b32 %0, 1, 0, p;\n\t}"
        : "=r"(done) : "r"(addr), "r"(parity) : "memory");
    if (!done) {
        asm volatile(
            "{\n\t.reg .pred P1;\n\t"
            "WL_%=:\n\t"
            "mbarrier.try_wait.parity.acquire.cluster.shared::cta.b64 P1, [%0], %1, 0x989680;\n\t"
            "@P1 bra.uni WD_%=;\n\t"
            "bra.uni WL_%=;\n\t"
            "WD_%=:\n\t}"
            :: "r"(addr), "r"(parity) : "memory");
    }
}

// ---------------------------------------------------------------------------
// Kernel A: pre[dir][t][g] = x[t] . w_ih[g] + b_ih[g] + b_hh[g]
// 64x64 tile, K=256, 256 threads, 4x4 register blocking.
// ---------------------------------------------------------------------------
__global__ __launch_bounds__(256) void gemm_pre_kernel(
    const float* __restrict__ x,
    const float* __restrict__ wf, const float* __restrict__ bif, const float* __restrict__ bhf,
    const float* __restrict__ wb, const float* __restrict__ bib, const float* __restrict__ bhb)
{
    int dir = blockIdx.z;
    const float* w  = dir ? wb  : wf;
    const float* b1 = dir ? bib : bif;
    const float* b2 = dir ? bhb : bhf;
    float* out = &g_pre[dir][0][0];

    int tok0 = blockIdx.x * 64;
    int g0   = blockIdx.y * 64;

    __shared__ float xs[16][64];
    __shared__ float wsm[16][64];

    int tid = threadIdx.x;
    int tx = tid & 15;
    int ty = tid >> 4;

    float acc[4][4];
#pragma unroll
    for (int i = 0; i < 4; i++)
#pragma unroll
        for (int j = 0; j < 4; j++) acc[i][j] = 0.f;

    int lr = tid >> 2;
    int lc = (tid & 3) * 4;

    for (int kk = 0; kk < D_IN; kk += 16) {
        float4 xv = *(const float4*)(x + (size_t)(tok0 + lr) * D_IN + kk + lc);
        float4 wv = *(const float4*)(w + (size_t)(g0  + lr) * D_IN + kk + lc);
        xs[lc + 0][lr] = xv.x; xs[lc + 1][lr] = xv.y; xs[lc + 2][lr] = xv.z; xs[lc + 3][lr] = xv.w;
        wsm[lc + 0][lr] = wv.x; wsm[lc + 1][lr] = wv.y; wsm[lc + 2][lr] = wv.z; wsm[lc + 3][lr] = wv.w;
        __syncthreads();
#pragma unroll
        for (int k = 0; k < 16; k++) {
            float4 a = *(const float4*)&xs[k][ty * 4];
            float4 b = *(const float4*)&wsm[k][tx * 4];
            float av[4] = {a.x, a.y, a.z, a.w};
            float bv[4] = {b.x, b.y, b.z, b.w};
#pragma unroll
            for (int i = 0; i < 4; i++)
#pragma unroll
                for (int j = 0; j < 4; j++)
                    acc[i][j] = fmaf(av[i], bv[j], acc[i][j]);
        }
        __syncthreads();
    }

    int g = g0 + tx * 4;
    float bb0 = b1[g + 0] + b2[g + 0];
    float bb1 = b1[g + 1] + b2[g + 1];
    float bb2 = b1[g + 2] + b2[g + 2];
    float bb3 = b1[g + 3] + b2[g + 3];
#pragma unroll
    for (int i = 0; i < 4; i++) {
        int tok = tok0 + ty * 4 + i;
        float4 o;
        o.x = acc[i][0] + bb0;
        o.y = acc[i][1] + bb1;
        o.z = acc[i][2] + bb2;
        o.w = acc[i][3] + bb3;
        *(float4*)(out + (size_t)tok * G4 + g) = o;
    }
}

// ---------------------------------------------------------------------------
// Kernel B: sequential LSTM, 2-CTA cluster per direction, GATE-ROW split
// (R7 structure) with an AGGREGATED mbarrier handshake instead of the
// per-step barrier.cluster (saves ~UCGABAR_WAIT 490 cyc + CCTL.IVALL flush).
//
// half = rank owns gate rows [half*256, half*256+256): half0 -> i,f; half1 -> g,o.
// 256 threads; thread t owns FULL row r = half*256+t (64 u64 weight regs).
// Per step:
//   v = pre + W_row . h                (4 independent 16-deep f32x2 chains)
//   vbuf[t] = v;  st.shared::cluster v -> peer part[buf][t]   (fire+forget)
//   __syncthreads            -- all 256 stores happen-before thread 0
//   t==0: mbarrier.arrive.release.cluster -> peer mbar[buf]   (ONE remote op;
//         release is cumulative through the BAR -> publishes all 256 stores)
//   all: acquire-wait local mbar[buf]   -- peer's 256 sums visible
//   t<HH: assemble (i,f,g,o) from {vbuf, part[buf]}; BOTH CTAs redundantly
//         (bitwise-identically) update c,h -> hbuf[np]; half0 writes g_hs
//   __syncthreads            -- hbuf[np] visible; vbuf reusable
// Backpressure (WAR on peer part[buf]): my step-u+2 stores are po-after my
// wait_{u+1}; that requires peer arrive_{u+1}, which is po-after peer's BAR1
// at u+1, which is po-after peer's step-u reads of part[buf]. Double-buffered
// barriers, count=1, re-inited every launch; no phase overrun (a CTA reaches
// arrive_{u+2} only after wait_{u+1}, which needs peer past arrive_{u+1}).
// ---------------------------------------------------------------------------
__global__ __launch_bounds__(256, 1) __cluster_dims__(2, 1, 1)
void lstm_kernel(
    const float* __restrict__ w_hh_f, const float* __restrict__ w_hh_b,
    const float* __restrict__ h0, const float* __restrict__ c0)
{
    __shared__ __align__(16) float hbuf[2][HH];
    __shared__ __align__(16) float vbuf[256];
    __shared__ __align__(16) float part[2][256];
    __shared__ __align__(8) unsigned long long mbar[2];

    int dir       = blockIdx.x >> 1;
    uint32_t half = blockIdx.x & 1u;
    int t = threadIdx.x;
    int r = (int)half * 256 + t;      // global gate row this thread owns

    const float* W = dir ? w_hh_b : w_hh_f;
    const ulonglong2* Wrow = (const ulonglong2*)(W + (size_t)r * HH);

    // Full row of weights in registers: 128 cols = 64 packed f32 pairs
    unsigned long long wp[64];
#pragma unroll
    for (int i = 0; i < 32; i++) {
        ulonglong2 v = Wrow[i];
        wp[2 * i]     = v.x;
        wp[2 * i + 1] = v.y;
    }

    if (t == 0) {
        uint32_t mb = smem_u32(&mbar[0]);
        asm volatile("mbarrier.init.shared.b64 [%0], %1;" :: "r"(mb), "r"(1u) : "memory");
        asm volatile("mbarrier.init.shared.b64 [%0], %1;" :: "r"(mb + 8), "r"(1u) : "memory");
    }
    float c_reg = 0.f;
    if (t < HH) {
        hbuf[0][t] = h0[dir * HH + t];
        c_reg      = c0[dir * HH + t];
    }
    __syncthreads();
    // cluster-wide: mbarriers + hbuf[0] visible before any remote traffic
    asm volatile("barrier.cluster.arrive.aligned;" ::: "memory");
    asm volatile("barrier.cluster.wait.aligned;" ::: "memory");

    // Peer smem addresses (computed once)
    uint32_t peer = half ^ 1u;
    uint32_t l_part = smem_u32(&part[0][0]);
    uint32_t l_mbar = smem_u32(&mbar[0]);
    uint32_t p_part, p_mbar;
    asm("mapa.shared::cluster.u32 %0, %1, %2;" : "=r"(p_part) : "r"(l_part), "r"(peer));
    asm("mapa.shared::cluster.u32 %0, %1, %2;" : "=r"(p_mbar) : "r"(l_mbar), "r"(peer));
    uint32_t p_store = p_part + (uint32_t)t * 4u;   // + buf*1024

    const float* P = &g_pre[dir][0][0];
    int row    = dir ? (TT - 1) : 0;
    int stride = dir ? -1 : 1;

    // 2-deep prefetch of this row's pre-activation stream
    float pf0, pf1;
    {
        int r1 = row + stride;
        int r1c = r1 < 0 ? 0 : (r1 >= TT ? TT - 1 : r1);
        pf0 = __ldg(P + (size_t)row * G4 + r);
        pf1 = __ldg(P + (size_t)r1c * G4 + r);
    }

    uint32_t ph0 = 0, ph1 = 0;
    int p = 0;

    for (int step = 0; step < TT; step++) {
        float pre_cur = pf0;
        pf0 = pf1;
        {
            int rr = row + 2 * stride;
            int rc = rr < 0 ? 0 : (rr >= TT ? TT - 1 : rr);
            pf1 = __ldg(P + (size_t)rc * G4 + r);
        }

        // Full-row matvec: 4 independent 16-deep f32x2 chains
        const ulonglong2* hp = (const ulonglong2*)&hbuf[p][0];
        unsigned long long a0, a1, a2, a3;
        asm("mov.b64 %0, {%1,%2};" : "=l"(a0) : "f"(pre_cur), "f"(0.0f));
        asm("mov.b64 %0, {%1,%2};" : "=l"(a1) : "f"(0.0f), "f"(0.0f));
        a2 = a1; a3 = a1;
#pragma unroll
        for (int i = 0; i < 32; i += 2) {
            ulonglong2 h0v = hp[i];
            ulonglong2 h1v = hp[i + 1];
            ffma2(a0, wp[2 * i],     h0v.x);
            ffma2(a1, wp[2 * i + 1], h0v.y);
            ffma2(a2, wp[2 * i + 2], h1v.x);
            ffma2(a3, wp[2 * i + 3], h1v.y);
        }
        float s0, s1, s2, s3, s4, s5, s6, s7;
        asm("mov.b64 {%0,%1}, %2;" : "=f"(s0), "=f"(s1) : "l"(a0));
        asm("mov.b64 {%0,%1}, %2;" : "=f"(s2), "=f"(s3) : "l"(a1));
        asm("mov.b64 {%0,%1}, %2;" : "=f"(s4), "=f"(s5) : "l"(a2));
        asm("mov.b64 {%0,%1}, %2;" : "=f"(s6), "=f"(s7) : "l"(a3));
        float v = ((s0 + s1) + (s2 + s3)) + ((s4 + s5) + (s6 + s7));

        const int buf = step & 1;
        vbuf[t] = v;
        asm volatile("st.shared::cluster.f32 [%0], %1;"
                     :: "r"(p_store + (uint32_t)(buf * 1024)), "f"(v) : "memory");

        __syncthreads();   // BAR1: all local+remote stores happen-before t0
        if (t == 0) {
            // ONE aggregated remote signal; release publishes all 256 stores
            asm volatile("mbarrier.arrive.release.cluster.shared::cluster.b64 _, [%0];"
                         :: "r"(p_mbar + (uint32_t)(buf * 8)) : "memory");
        }
        // acquire-wait: peer's gate sums for this step are now visible
        if (buf == 0) { mbar_wait_cluster(l_mbar, ph0);     ph0 ^= 1u; }
        else          { mbar_wait_cluster(l_mbar + 8, ph1); ph1 ^= 1u; }

        int np = p ^ 1;
        if (t < HH) {
            float gi, gf, gg, go;
            if (half == 0) {
                gi = vbuf[t];        gf = vbuf[HH + t];
                gg = part[buf][t];   go = part[buf][HH + t];
            } else {
                gi = part[buf][t];   gf = part[buf][HH + t];
                gg = vbuf[t];        go = vbuf[HH + t];
            }
            float iv = fsigmoid(gi);
            float fv = fsigmoid(gf);
            float gv = ftanh(gg);
            float ov = fsigmoid(go);
            c_reg = fv * c_reg + iv * gv;
            float hv = ov * ftanh(c_reg);
            hbuf[np][t] = hv;
            if (half == 0) g_hs[row][HH * dir + t] = hv;
        }
        __syncthreads();   // BAR2: hbuf[np] visible; vbuf safe next step

        p = np;
        row += stride;
    }

    // no CTA may exit while peer can still touch its smem
    asm volatile("barrier.cluster.arrive.aligned;" ::: "memory");
    asm volatile("barrier.cluster.wait.aligned;" ::: "memory");
}

// ---------------------------------------------------------------------------
// Kernel C: att[t] = sum_d tanh( (x @ w_omega)[t,d] ) * u_omega[d]
// ---------------------------------------------------------------------------
#define ATTN_SMEM ((64 * HID + 16 * 257) * 4)

__global__ __launch_bounds__(256) void attn_kernel(
    const float* __restrict__ w_omega, const float* __restrict__ u_omega)
{
    extern __shared__ float smc[];
    float* xs  = smc;
    float* red = smc + 64 * HID;

    int tid  = threadIdx.x;
    int tok0 = blockIdx.x * 64;

    const float4* src = (const float4*)&g_hs[tok0][0];
    float4* dst = (float4*)xs;
    for (int idx = tid; idx < 64 * HID / 4; idx += 256) dst[idx] = src[idx];
    __syncthreads();

    float uo = u_omega[tid];

    for (int c = 0; c < 4; c++) {
        float acc[16];
#pragma unroll
        for (int t = 0; t < 16; t++) acc[t] = 0.f;
        const float* xbase = xs + (c * 16) * HID;

        for (int k = 0; k < HID; k += 4) {
            float w0 = __ldg(w_omega + (k + 0) * HID + tid);
            float w1 = __ldg(w_omega + (k + 1) * HID + tid);
            float w2 = __ldg(w_omega + (k + 2) * HID + tid);
            float w3 = __ldg(w_omega + (k + 3) * HID + tid);
#pragma unroll
            for (int t = 0; t < 16; t++) {
                float4 xv = *(const float4*)(xbase + t * HID + k);
                acc[t] = fmaf(xv.x, w0,
                         fmaf(xv.y, w1,
                         fmaf(xv.z, w2,
                         fmaf(xv.w, w3, acc[t]))));
            }
        }
#pragma unroll
        for (int t = 0; t < 16; t++)
            red[t * 257 + tid] = tanh_acc(acc[t]) * uo;
        __syncthreads();
        if (tid < 16) {
            float s = 0.f;
            for (int jx = 0; jx < HID; jx++) s += red[tid * 257 + jx];
            g_att[tok0 + c * 16 + tid] = s;
        }
        __syncthreads();
    }
}

// ---------------------------------------------------------------------------
// Kernel D: per-segment softmax pooling + tag projection
// ---------------------------------------------------------------------------
__global__ __launch_bounds__(256) void seg_pool_kernel(
    const int* __restrict__ mask,
    const float* __restrict__ w_tag, const float* __restrict__ b_tag,
    float* __restrict__ out)
{
    int s = blockIdx.x;
    int tid = threadIdx.x;
    int lo = (s == 0) ? 0 : mask[s - 1];
    int hi = (s == NSEG - 1) ? TT : mask[s];

    if (lo >= hi) {
        if (tid < TAGS) out[s * TAGS + tid] = b_tag[tid];
        return;
    }

    __shared__ float red[256];
    __shared__ float e_sm[256];
    __shared__ float ctx[256];

    float m = -3.4e38f;
    for (int i = lo + tid; i < hi; i += 256) m = fmaxf(m, g_att[i]);
    red[tid] = m; __syncthreads();
    for (int w = 128; w > 0; w >>= 1) {
        if (tid < w) red[tid] = fmaxf(red[tid], red[tid + w]);
        __syncthreads();
    }
    m = red[0]; __syncthreads();

    float z = 0.f;
    for (int i = lo + tid; i < hi; i += 256) z += __expf(g_att[i] - m);
    red[tid] = z; __syncthreads();
    for (int w = 128; w > 0; w >>= 1) {
        if (tid < w) red[tid] += red[tid + w];
        __syncthreads();
    }
    z = red[0]; __syncthreads();

    float acc = 0.f;
    for (int base = lo; base < hi; base += 256) {
        int i = base + tid;
        e_sm[tid] = (i < hi) ? __expf(g_att[i] - m) : 0.f;
        __syncthreads();
        int n = min(256, hi - base);
        for (int jx = 0; jx < n; jx++)
            acc = fmaf(g_hs[base + jx][tid], e_sm[jx], acc);
        __syncthreads();
    }
    ctx[tid] = acc / z;
    __syncthreads();

    if (tid < TAGS) {
        float rr = b_tag[tid];
        for (int d = 0; d < HID; d++) rr = fmaf(ctx[d], w_tag[tid * HID + d], rr);
        out[s * TAGS + tid] = rr;
    }
}

// ---------------------------------------------------------------------------
extern "C" void kernel_launch(void* const* d_in, const int* in_sizes, int n_in,
                              void* d_out, int out_size)
{
    const float* sentence = (const float*)d_in[0];
    const float* h0       = (const float*)d_in[1];
    const float* c0       = (const float*)d_in[2];
    const float* w_ih_f   = (const float*)d_in[3];
    const float* w_hh_f   = (const float*)d_in[4];
    const float* b_ih_f   = (const float*)d_in[5];
    const float* b_hh_f   = (const float*)d_in[6];
    const float* w_ih_b   = (const float*)d_in[7];
    const float* w_hh_b   = (const float*)d_in[8];
    const float* b_ih_b   = (const float*)d_in[9];
    const float* b_hh_b   = (const float*)d_in[10];
    const float* w_omega  = (const float*)d_in[11];
    const float* u_omega  = (const float*)d_in[12];
    const float* w_tag    = (const float*)d_in[13];
    const float* b_tag    = (const float*)d_in[14];
    const int*   doc_mask = (const int*)d_in[15];
    float* out = (float*)d_out;

    cudaFuncSetAttribute(attn_kernel, cudaFuncAttributeMaxDynamicSharedMemorySize, ATTN_SMEM);

    dim3 ggrid(TT / 64, G4 / 64, 2);
    gemm_pre_kernel<<<ggrid, 256>>>(sentence, w_ih_f, b_ih_f, b_hh_f,
                                    w_ih_b, b_ih_b, b_hh_b);
    lstm_kernel<<<4, 256>>>(w_hh_f, w_hh_b, h0, c0);
    attn_kernel<<<TT / 64, 256, ATTN_SMEM>>>(w_omega, u_omega);
    seg_pool_kernel<<<NSEG, 256>>>(doc_mask, w_tag, b_tag, out);
}

// round 10
// speedup vs baseline: 1.2484x; 1.2484x over previous
#include <cuda_runtime.h>
#include <math.h>
#include <stdint.h>

// Problem constants
#define TT   131072   // tokens
#define D_IN 256      // input dim
#define HH   128      // per-direction hidden
#define G4   512      // 4*HH gate rows
#define HID  256      // bidirectional hidden
#define TAGS 10
#define NSEG 1024

// Scratch (device globals — no allocation allowed in kernel_launch)
__device__ float g_pre[2][TT][G4];   // pre-activations per direction (original token order)
__device__ float g_hs[TT][HID];      // [hf | hb] concatenated
__device__ float g_att[TT];          // attention logits

// Fast activations: __expf (EX2) + __fdividef (~2 ulp). Inf-safe saturation.
__device__ __forceinline__ float fsigmoid(float x) {
    return __fdividef(1.0f, 1.0f + __expf(-x));
}
__device__ __forceinline__ float ftanh(float x) {
    return 1.0f - __fdividef(2.0f, __expf(2.0f * x) + 1.0f);
}
// Accurate tanh for the (non-recurrent) attention path
__device__ __forceinline__ float tanh_acc(float x) {
    return 1.0f - 2.0f / (__expf(2.0f * x) + 1.0f);
}

// Packed dual-FMA (Blackwell f32x2). acc.{lo,hi} += a.{lo,hi} * b.{lo,hi}
__device__ __forceinline__ void ffma2(unsigned long long& acc,
                                      unsigned long long a,
                                      unsigned long long b) {
    asm("fma.rn.f32x2 %0, %1, %2, %0;" : "+l"(acc) : "l"(a), "l"(b));
}

__device__ __forceinline__ uint32_t smem_u32(const void* p) {
    uint32_t a;
    asm("{ .reg .u64 t; cvta.to.shared.u64 t, %1; cvt.u32.u64 %0, t; }"
        : "=r"(a) : "l"(p));
    return a;
}

// ---------------------------------------------------------------------------
// Kernel A: pre[dir][t][g] = x[t] . w_ih[g] + b_ih[g] + b_hh[g]
// 64x64 tile, K=256, 256 threads, 4x4 register blocking.
// ---------------------------------------------------------------------------
__global__ __launch_bounds__(256) void gemm_pre_kernel(
    const float* __restrict__ x,
    const float* __restrict__ wf, const float* __restrict__ bif, const float* __restrict__ bhf,
    const float* __restrict__ wb, const float* __restrict__ bib, const float* __restrict__ bhb)
{
    int dir = blockIdx.z;
    const float* w  = dir ? wb  : wf;
    const float* b1 = dir ? bib : bif;
    const float* b2 = dir ? bhb : bhf;
    float* out = &g_pre[dir][0][0];

    int tok0 = blockIdx.x * 64;
    int g0   = blockIdx.y * 64;

    __shared__ float xs[16][64];
    __shared__ float wsm[16][64];

    int tid = threadIdx.x;
    int tx = tid & 15;
    int ty = tid >> 4;

    float acc[4][4];
#pragma unroll
    for (int i = 0; i < 4; i++)
#pragma unroll
        for (int j = 0; j < 4; j++) acc[i][j] = 0.f;

    int lr = tid >> 2;
    int lc = (tid & 3) * 4;

    for (int kk = 0; kk < D_IN; kk += 16) {
        float4 xv = *(const float4*)(x + (size_t)(tok0 + lr) * D_IN + kk + lc);
        float4 wv = *(const float4*)(w + (size_t)(g0  + lr) * D_IN + kk + lc);
        xs[lc + 0][lr] = xv.x; xs[lc + 1][lr] = xv.y; xs[lc + 2][lr] = xv.z; xs[lc + 3][lr] = xv.w;
        wsm[lc + 0][lr] = wv.x; wsm[lc + 1][lr] = wv.y; wsm[lc + 2][lr] = wv.z; wsm[lc + 3][lr] = wv.w;
        __syncthreads();
#pragma unroll
        for (int k = 0; k < 16; k++) {
            float4 a = *(const float4*)&xs[k][ty * 4];
            float4 b = *(const float4*)&wsm[k][tx * 4];
            float av[4] = {a.x, a.y, a.z, a.w};
            float bv[4] = {b.x, b.y, b.z, b.w};
#pragma unroll
            for (int i = 0; i < 4; i++)
#pragma unroll
                for (int j = 0; j < 4; j++)
                    acc[i][j] = fmaf(av[i], bv[j], acc[i][j]);
        }
        __syncthreads();
    }

    int g = g0 + tx * 4;
    float bb0 = b1[g + 0] + b2[g + 0];
    float bb1 = b1[g + 1] + b2[g + 1];
    float bb2 = b1[g + 2] + b2[g + 2];
    float bb3 = b1[g + 3] + b2[g + 3];
#pragma unroll
    for (int i = 0; i < 4; i++) {
        int tok = tok0 + ty * 4 + i;
        float4 o;
        o.x = acc[i][0] + bb0;
        o.y = acc[i][1] + bb1;
        o.z = acc[i][2] + bb2;
        o.w = acc[i][3] + bb3;
        *(float4*)(out + (size_t)tok * G4 + g) = o;
    }
}

// ---------------------------------------------------------------------------
// Kernel B: sequential LSTM, 4-CTA cluster per direction, GATE split.
//
// grid = 8 CTAs, cluster dims 4: cluster {0..3}=fwd, {4..7}=bwd.
// rank = gate: CTA q owns gate q's 128 rows [q*128, q*128+128).
// 128 threads; thread t owns FULL row r = rank*128+t:
//   128 weight cols = 64 u64 regs (~170 regs total at 128 thr -> no spill).
// Per step (R7-proven protocol, widened to 4 CTAs):
//   v = pre[r] + W_row . h            (4 independent 16-deep f32x2 chains)
//   gbuf[buf][rank][t] = v  (local)  +  st.shared::cluster to the 3 peers'
//   gbuf[buf][rank][t]                (fire-and-forget remote stores)
//   barrier.cluster arrive+wait       (each thread's own stores released by
//                                      its own arrive; wait = acquire)
//   all threads: gi/gf/gg/go = gbuf[buf][0..3][t]; ALL 4 CTAs redundantly
//   (bitwise-identically) update c_reg, h -> hbuf[np][t]; rank 0 writes g_hs
//   __syncthreads                      (hbuf[np] visible next matvec)
// WAR on gbuf[buf]: peers read gbuf[buf] at step u after barrier_u and before
// their arrive_{u+1} (program order); my step-u+2 stores to gbuf[buf] are
// po-after my wait_{u+1}, which requires all arrives_{u+1}. Double-buffered.
// ---------------------------------------------------------------------------
__global__ __launch_bounds__(128, 1) __cluster_dims__(4, 1, 1)
void lstm_kernel(
    const float* __restrict__ w_hh_f, const float* __restrict__ w_hh_b,
    const float* __restrict__ h0, const float* __restrict__ c0)
{
    __shared__ __align__(16) float hbuf[2][HH];
    __shared__ __align__(16) float gbuf[2][4][HH];   // [buf][src gate][j]

    int dir       = blockIdx.x >> 2;
    uint32_t rank = blockIdx.x & 3u;     // == gate index this CTA owns
    int t = threadIdx.x;                 // 0..127 == h index j and row-in-gate
    int r = (int)rank * HH + t;          // global gate row this thread owns

    const float* W = dir ? w_hh_b : w_hh_f;
    const ulonglong2* Wrow = (const ulonglong2*)(W + (size_t)r * HH);

    // Full row of weights in registers: 128 cols = 64 packed f32 pairs
    unsigned long long wp[64];
#pragma unroll
    for (int i = 0; i < 32; i++) {
        ulonglong2 v = Wrow[i];
        wp[2 * i]     = v.x;
        wp[2 * i + 1] = v.y;
    }

    // init h, c (every thread owns h/c index t; all CTAs redundant)
    hbuf[0][t] = h0[dir * HH + t];
    float c_reg = c0[dir * HH + t];
    __syncthreads();

    // Peer gbuf addresses for my gate slot (3 peers, computed once)
    uint32_t l_gbuf = smem_u32(&gbuf[0][0][0]);
    uint32_t my_off = (rank * HH + (uint32_t)t) * 4u;   // + buf*4*HH*4
    uint32_t pg[3];
    {
        int n = 0;
#pragma unroll
        for (uint32_t q = 0; q < 4; q++) {
            if (q != rank) {
                uint32_t b;
                asm("mapa.shared::cluster.u32 %0, %1, %2;" : "=r"(b) : "r"(l_gbuf), "r"(q));
                pg[n++] = b + my_off;
            }
        }
    }

    // Align cluster before stepped protocol (hbuf[0] init visible where needed
    // is local-only; barrier aligns pacing)
    asm volatile("barrier.cluster.arrive.aligned;" ::: "memory");
    asm volatile("barrier.cluster.wait.aligned;" ::: "memory");

    const float* P = &g_pre[dir][0][0];
    int row    = dir ? (TT - 1) : 0;
    int stride = dir ? -1 : 1;

    // 2-deep prefetch of this row's pre-activation stream
    float pf0, pf1;
    {
        int r1 = row + stride;
        int r1c = r1 < 0 ? 0 : (r1 >= TT ? TT - 1 : r1);
        pf0 = __ldg(P + (size_t)row * G4 + r);
        pf1 = __ldg(P + (size_t)r1c * G4 + r);
    }

    int p = 0;

    for (int step = 0; step < TT; step++) {
        float pre_cur = pf0;
        pf0 = pf1;
        {
            int rr = row + 2 * stride;
            int rc = rr < 0 ? 0 : (rr >= TT ? TT - 1 : rr);
            pf1 = __ldg(P + (size_t)rc * G4 + r);
        }

        // Full-row matvec: 4 independent 16-deep f32x2 chains
        const ulonglong2* hp = (const ulonglong2*)&hbuf[p][0];
        unsigned long long a0, a1, a2, a3;
        asm("mov.b64 %0, {%1,%2};" : "=l"(a0) : "f"(pre_cur), "f"(0.0f));
        asm("mov.b64 %0, {%1,%2};" : "=l"(a1) : "f"(0.0f), "f"(0.0f));
        a2 = a1; a3 = a1;
#pragma unroll
        for (int i = 0; i < 32; i += 2) {
            ulonglong2 h0v = hp[i];
            ulonglong2 h1v = hp[i + 1];
            ffma2(a0, wp[2 * i],     h0v.x);
            ffma2(a1, wp[2 * i + 1], h0v.y);
            ffma2(a2, wp[2 * i + 2], h1v.x);
            ffma2(a3, wp[2 * i + 3], h1v.y);
        }
        float s0, s1, s2, s3, s4, s5, s6, s7;
        asm("mov.b64 {%0,%1}, %2;" : "=f"(s0), "=f"(s1) : "l"(a0));
        asm("mov.b64 {%0,%1}, %2;" : "=f"(s2), "=f"(s3) : "l"(a1));
        asm("mov.b64 {%0,%1}, %2;" : "=f"(s4), "=f"(s5) : "l"(a2));
        asm("mov.b64 {%0,%1}, %2;" : "=f"(s6), "=f"(s7) : "l"(a3));
        float v = ((s0 + s1) + (s2 + s3)) + ((s4 + s5) + (s6 + s7));

        const int buf = step & 1;
        const uint32_t boff = (uint32_t)(buf * 4 * HH * 4);
        gbuf[buf][rank][t] = v;
        asm volatile("st.shared::cluster.f32 [%0], %1;" :: "r"(pg[0] + boff), "f"(v) : "memory");
        asm volatile("st.shared::cluster.f32 [%0], %1;" :: "r"(pg[1] + boff), "f"(v) : "memory");
        asm volatile("st.shared::cluster.f32 [%0], %1;" :: "r"(pg[2] + boff), "f"(v) : "memory");

        // Cluster barrier: own stores released by own arrive; wait = acquire.
        asm volatile("barrier.cluster.arrive.aligned;" ::: "memory");
        asm volatile("barrier.cluster.wait.aligned;" ::: "memory");

        int np = p ^ 1;
        {
            float gi = gbuf[buf][0][t];
            float gf = gbuf[buf][1][t];
            float gg = gbuf[buf][2][t];
            float go = gbuf[buf][3][t];
            float iv = fsigmoid(gi);
            float fv = fsigmoid(gf);
            float gv = ftanh(gg);
            float ov = fsigmoid(go);
            c_reg = fv * c_reg + iv * gv;
            float hv = ov * ftanh(c_reg);
            hbuf[np][t] = hv;
            if (rank == 0) g_hs[row][HH * dir + t] = hv;
        }
        __syncthreads();   // hbuf[np] visible for next matvec

        p = np;
        row += stride;
    }

    // no CTA may exit while peers can still touch its smem
    asm volatile("barrier.cluster.arrive.aligned;" ::: "memory");
    asm volatile("barrier.cluster.wait.aligned;" ::: "memory");
}

// ---------------------------------------------------------------------------
// Kernel C: att[t] = sum_d tanh( (x @ w_omega)[t,d] ) * u_omega[d]
// ---------------------------------------------------------------------------
#define ATTN_SMEM ((64 * HID + 16 * 257) * 4)

__global__ __launch_bounds__(256) void attn_kernel(
    const float* __restrict__ w_omega, const float* __restrict__ u_omega)
{
    extern __shared__ float smc[];
    float* xs  = smc;
    float* red = smc + 64 * HID;

    int tid  = threadIdx.x;
    int tok0 = blockIdx.x * 64;

    const float4* src = (const float4*)&g_hs[tok0][0];
    float4* dst = (float4*)xs;
    for (int idx = tid; idx < 64 * HID / 4; idx += 256) dst[idx] = src[idx];
    __syncthreads();

    float uo = u_omega[tid];

    for (int c = 0; c < 4; c++) {
        float acc[16];
#pragma unroll
        for (int t = 0; t < 16; t++) acc[t] = 0.f;
        const float* xbase = xs + (c * 16) * HID;

        for (int k = 0; k < HID; k += 4) {
            float w0 = __ldg(w_omega + (k + 0) * HID + tid);
            float w1 = __ldg(w_omega + (k + 1) * HID + tid);
            float w2 = __ldg(w_omega + (k + 2) * HID + tid);
            float w3 = __ldg(w_omega + (k + 3) * HID + tid);
#pragma unroll
            for (int t = 0; t < 16; t++) {
                float4 xv = *(const float4*)(xbase + t * HID + k);
                acc[t] = fmaf(xv.x, w0,
                         fmaf(xv.y, w1,
                         fmaf(xv.z, w2,
                         fmaf(xv.w, w3, acc[t]))));
            }
        }
#pragma unroll
        for (int t = 0; t < 16; t++)
            red[t * 257 + tid] = tanh_acc(acc[t]) * uo;
        __syncthreads();
        if (tid < 16) {
            float s = 0.f;
            for (int jx = 0; jx < HID; jx++) s += red[tid * 257 + jx];
            g_att[tok0 + c * 16 + tid] = s;
        }
        __syncthreads();
    }
}

// ---------------------------------------------------------------------------
// Kernel D: per-segment softmax pooling + tag projection
// ---------------------------------------------------------------------------
__global__ __launch_bounds__(256) void seg_pool_kernel(
    const int* __restrict__ mask,
    const float* __restrict__ w_tag, const float* __restrict__ b_tag,
    float* __restrict__ out)
{
    int s = blockIdx.x;
    int tid = threadIdx.x;
    int lo = (s == 0) ? 0 : mask[s - 1];
    int hi = (s == NSEG - 1) ? TT : mask[s];

    if (lo >= hi) {
        if (tid < TAGS) out[s * TAGS + tid] = b_tag[tid];
        return;
    }

    __shared__ float red[256];
    __shared__ float e_sm[256];
    __shared__ float ctx[256];

    float m = -3.4e38f;
    for (int i = lo + tid; i < hi; i += 256) m = fmaxf(m, g_att[i]);
    red[tid] = m; __syncthreads();
    for (int w = 128; w > 0; w >>= 1) {
        if (tid < w) red[tid] = fmaxf(red[tid], red[tid + w]);
        __syncthreads();
    }
    m = red[0]; __syncthreads();

    float z = 0.f;
    for (int i = lo + tid; i < hi; i += 256) z += __expf(g_att[i] - m);
    red[tid] = z; __syncthreads();
    for (int w = 128; w > 0; w >>= 1) {
        if (tid < w) red[tid] += red[tid + w];
        __syncthreads();
    }
    z = red[0]; __syncthreads();

    float acc = 0.f;
    for (int base = lo; base < hi; base += 256) {
        int i = base + tid;
        e_sm[tid] = (i < hi) ? __expf(g_att[i] - m) : 0.f;
        __syncthreads();
        int n = min(256, hi - base);
        for (int jx = 0; jx < n; jx++)
            acc = fmaf(g_hs[base + jx][tid], e_sm[jx], acc);
        __syncthreads();
    }
    ctx[tid] = acc / z;
    __syncthreads();

    if (tid < TAGS) {
        float rr = b_tag[tid];
        for (int d = 0; d < HID; d++) rr = fmaf(ctx[d], w_tag[tid * HID + d], rr);
        out[s * TAGS + tid] = rr;
    }
}

// ---------------------------------------------------------------------------
extern "C" void kernel_launch(void* const* d_in, const int* in_sizes, int n_in,
                              void* d_out, int out_size)
{
    const float* sentence = (const float*)d_in[0];
    const float* h0       = (const float*)d_in[1];
    const float* c0       = (const float*)d_in[2];
    const float* w_ih_f   = (const float*)d_in[3];
    const float* w_hh_f   = (const float*)d_in[4];
    const float* b_ih_f   = (const float*)d_in[5];
    const float* b_hh_f   = (const float*)d_in[6];
    const float* w_ih_b   = (const float*)d_in[7];
    const float* w_hh_b   = (const float*)d_in[8];
    const float* b_ih_b   = (const float*)d_in[9];
    const float* b_hh_b   = (const float*)d_in[10];
    const float* w_omega  = (const float*)d_in[11];
    const float* u_omega  = (const float*)d_in[12];
    const float* w_tag    = (const float*)d_in[13];
    const float* b_tag    = (const float*)d_in[14];
    const int*   doc_mask = (const int*)d_in[15];
    float* out = (float*)d_out;

    cudaFuncSetAttribute(attn_kernel, cudaFuncAttributeMaxDynamicSharedMemorySize, ATTN_SMEM);

    dim3 ggrid(TT / 64, G4 / 64, 2);
    gemm_pre_kernel<<<ggrid, 256>>>(sentence, w_ih_f, b_ih_f, b_hh_f,
                                    w_ih_b, b_ih_b, b_hh_b);
    lstm_kernel<<<8, 128>>>(w_hh_f, w_hh_b, h0, c0);
    attn_kernel<<<TT / 64, 256, ATTN_SMEM>>>(w_omega, u_omega);
    seg_pool_kernel<<<NSEG, 256>>>(doc_mask, w_tag, b_tag, out);
}